// round 8
// baseline (speedup 1.0000x reference)
#include <cuda_runtime.h>
#include <math.h>

#define RR 273
#define CC 256
#define KK 219
#define NTHREADS 256
#define SORTN 512
#define NWARPS 8
#define HB 280          // per-warp histogram stride (>= RR)
#define FULLM 0xFFFFFFFFu
#define EMAX (1024 * 273 * 32)

__device__ int g_edge_is64;
__device__ unsigned int g_packed[EMAX];   // packed local edge ids, L2-resident (35.8MB)

__global__ void probe_dtype_kernel(const int* ei32) {
    if (threadIdx.x == 0) {
        int all_zero = 1;
        #pragma unroll
        for (int i = 1; i < 64; i += 2)
            if (ei32[i] != 0) { all_zero = 0; break; }
        g_edge_is64 = all_zero;
    }
}

// Convert edge_index -> packed (src_local<<16 | dst_local) u32 scratch.
__global__ __launch_bounds__(256)
void pack_edges_kernel(const void* __restrict__ edge_index, long long E) {
    const int is64 = g_edge_is64;
    long long i = (long long)blockIdx.x * blockDim.x + threadIdx.x;
    long long stride = (long long)gridDim.x * blockDim.x;
    if (is64) {
        const long long* p = (const long long*)edge_index;
        for (; i < E; i += stride) {
            unsigned s = (unsigned)p[i];
            unsigned d = (unsigned)p[E + i];
            g_packed[i] = ((s % RR) << 16) | (d % RR);
        }
    } else {
        const int* p = (const int*)edge_index;
        for (; i < E; i += stride) {
            unsigned s = (unsigned)p[i];
            unsigned d = (unsigned)p[E + i];
            g_packed[i] = ((s % RR) << 16) | (d % RR);
        }
    }
}

__device__ __forceinline__ unsigned int ord_f32(float f) {
    unsigned int u = __float_as_uint(f);
    return (u & 0x80000000u) ? ~u : (u | 0x80000000u);
}

__global__ __launch_bounds__(NTHREADS, 5)
void sagpool_kernel(const float* __restrict__ x,
                    const float* __restrict__ Wp,
                    const float* __restrict__ bp,
                    float* __restrict__ out,
                    long long E, int epg,
                    size_t off_ei, size_t off_keep, size_t off_batch,
                    size_t off_perm, size_t off_score)
{
    extern __shared__ char smem[];
    // ---- layout (must match host sizing) ----
    float* wsh   = (float*)smem;                        // 256 floats
    float* h_s   = wsh + CC;                            // 288
    float* dis_s = h_s + 288;                           // 288
    float* sc_s  = dis_s + 288;                         // 288
    int* indeg_s = (int*)(sc_s + 288);                  // 288
    int* start_s = indeg_s + 288;                       // 288
    int* newid_s = start_s + 288;                       // 288
    unsigned short* hist = (unsigned short*)(newid_s + 288);  // 8*HB u16 = 4480B
    // union region (8B aligned): ssrc (epg u16) alive until score end;
    // keys (512 u64) written after score.
    char* ub = (char*)(hist + NWARPS * HB);
    ub = (char*)(((size_t)ub + 7) & ~(size_t)7);
    unsigned short* ssrc = (unsigned short*)ub;
    unsigned long long* keys = (unsigned long long*)ub;

    const int tid  = threadIdx.x;
    const int lane = tid & 31;
    const int warp = tid >> 5;
    const int g    = blockIdx.x;
    const long long gbase = (long long)g * RR;
    const long long ebase = (long long)g * epg;

    // ---- stage W, init small arrays ----
    if (tid < CC) wsh[tid] = Wp[tid];
    for (int v = tid; v < RR; v += NTHREADS) newid_s[v] = -1;
    for (int i = tid; i < NWARPS * HB; i += NTHREADS) hist[i] = 0;
    __syncthreads();

    // ---- phase A: h[v] as Eigen NEON row-major gemv (evalGemv path):
    //      4-lane packet accumulator, vfmaq (fused FMA),
    //      predux: (a0+a2)+(a1+a3).  Direct gmem row loads.
    {
        const float4* w4 = (const float4*)wsh;
        {
            int row = tid;            // always < RR (256 < 273)
            const float4* xr = (const float4*)(x + ((size_t)(gbase + row)) * CC);
            float a0 = 0.f, a1 = 0.f, a2 = 0.f, a3 = 0.f;
            #pragma unroll 4
            for (int i = 0; i < 64; i++) {
                float4 v = xr[i];
                float4 w = w4[i];
                a0 = fmaf(v.x, w.x, a0);
                a1 = fmaf(v.y, w.y, a1);
                a2 = fmaf(v.z, w.z, a2);
                a3 = fmaf(v.w, w.w, a3);
            }
            h_s[row] = __fadd_rn(__fadd_rn(a0, a2), __fadd_rn(a1, a3));
        }
        int row2 = tid + NTHREADS;
        if (row2 < RR) {
            const float4* xr = (const float4*)(x + ((size_t)(gbase + row2)) * CC);
            float a0 = 0.f, a1 = 0.f, a2 = 0.f, a3 = 0.f;
            #pragma unroll 4
            for (int i = 0; i < 64; i++) {
                float4 v = xr[i];
                float4 w = w4[i];
                a0 = fmaf(v.x, w.x, a0);
                a1 = fmaf(v.y, w.y, a1);
                a2 = fmaf(v.z, w.z, a2);
                a3 = fmaf(v.w, w.w, a3);
            }
            h_s[row2] = __fadd_rn(__fadd_rn(a0, a2), __fadd_rn(a1, a3));
        }
    }

    // ---- stable counting sort of edges by dst (edges read from L2 scratch) ----
    const int per = (((epg + NWARPS - 1) / NWARPS) + 31) & ~31;
    const int cbeg = warp * per;
    const int cend = min(epg, cbeg + per);

    // pass 1: per-warp-chunk histograms
    for (int base = cbeg; base < cend; base += 32) {
        int e = base + lane;
        bool act = e < cend;
        unsigned v = act ? g_packed[ebase + e] : 0u;
        int dst = act ? (int)(v & 0xFFFFu) : (512 + lane);
        unsigned m = __match_any_sync(FULLM, dst);
        int leader = __ffs(m) - 1;
        if (act && lane == leader)
            hist[warp * HB + dst] = (unsigned short)(hist[warp * HB + dst] + __popc(m));
        __syncwarp();
    }
    __syncthreads();

    // in-degree, dis = 1/sqrt(deg) (deg includes self-loop), both correctly rounded
    for (int v = tid; v < RR; v += NTHREADS) {
        int s = 0;
        #pragma unroll
        for (int w2 = 0; w2 < NWARPS; w2++) s += hist[w2 * HB + v];
        indeg_s[v] = s;
        dis_s[v] = __fdiv_rn(1.0f, __fsqrt_rn((float)(s + 1)));
    }
    __syncthreads();

    // exclusive scan of indeg -> start offsets (warp 0)
    if (warp == 0) {
        int lo = lane * 9;
        int acc = 0;
        #pragma unroll
        for (int i = 0; i < 9; i++) { int v = lo + i; if (v < RR) acc += indeg_s[v]; }
        int ex = acc;
        #pragma unroll
        for (int o = 1; o < 32; o <<= 1) {
            int t = __shfl_up_sync(FULLM, ex, o);
            if (lane >= o) ex += t;
        }
        ex -= acc;
        int run = ex;
        #pragma unroll
        for (int i = 0; i < 9; i++) {
            int v = lo + i;
            if (v < RR) { start_s[v] = run; run += indeg_s[v]; }
        }
    }
    __syncthreads();

    // per-(warp,dst) base pointers (in place, u16 positions < 8736)
    for (int v = tid; v < RR; v += NTHREADS) {
        int s = start_s[v];
        #pragma unroll
        for (int w2 = 0; w2 < NWARPS; w2++) {
            int t = hist[w2 * HB + v];
            hist[w2 * HB + v] = (unsigned short)s;
            s += t;
        }
    }
    __syncthreads();

    // pass 2: stable placement of src ids into per-dst lists
    for (int base = cbeg; base < cend; base += 32) {
        int e = base + lane;
        bool act = e < cend;
        unsigned v = act ? g_packed[ebase + e] : 0u;
        int dst = act ? (int)(v & 0xFFFFu) : (512 + lane);
        unsigned m = __match_any_sync(FULLM, dst);
        int rank = __popc(m & ((1u << lane) - 1u));
        int pos = 0;
        if (act) pos = (int)hist[warp * HB + dst] + rank;
        __syncwarp();
        if (act) ssrc[pos] = (unsigned short)(v >> 16);
        int leader = __ffs(m) - 1;
        if (act && lane == leader)
            hist[warp * HB + dst] = (unsigned short)(hist[warp * HB + dst] + __popc(m));
        __syncwarp();
    }
    __syncthreads();

    // ---- score: strictly sequential in reference scatter order ----
    const float bval = bp[0];
    for (int v = tid; v < RR; v += NTHREADS) {
        float dv = dis_s[v];
        float acc = 0.f;
        int st = start_s[v], n = indeg_s[v];
        for (int i = 0; i < n; i++) {
            int src = ssrc[st + i];
            float c = __fmul_rn(__fmul_rn(dis_s[src], dv), h_s[src]);
            acc = __fadd_rn(acc, c);
        }
        float selfc = __fmul_rn(__fmul_rn(dv, dv), h_s[v]);
        acc = __fadd_rn(acc, selfc);
        float sc = __fadd_rn(acc, bval);
        sc_s[v] = sc;
        out[off_score + (size_t)gbase + v] = sc;
    }
    __syncthreads();

    // ---- sort keys (overlay: ssrc is dead now) ----
    for (int v = tid; v < SORTN; v += NTHREADS) {
        if (v < RR) {
            keys[v] = ((unsigned long long)ord_f32(sc_s[v]) << 32)
                      | (unsigned long long)(0x1FFu - (unsigned)v);
        } else keys[v] = 0ull;
    }

    // bitonic sort descending (ties -> lower index first)
    for (int kk = 2; kk <= SORTN; kk <<= 1) {
        for (int j = kk >> 1; j > 0; j >>= 1) {
            __syncthreads();
            for (int t = tid; t < SORTN; t += NTHREADS) {
                int ixj = t ^ j;
                if (ixj > t) {
                    bool desc = ((t & kk) == 0);
                    unsigned long long a = keys[t], b2 = keys[ixj];
                    if ((a < b2) == desc) { keys[t] = b2; keys[ixj] = a; }
                }
            }
        }
    }
    __syncthreads();

    // ---- new-id map ----
    if (tid < KK) {
        int v = 0x1FF - (int)(keys[tid] & 0xFFFFFFFFull);
        newid_s[v] = tid;
    }
    __syncthreads();

    // ---- x_new / perm / batch_new ----
    for (int k = warp; k < KK; k += NWARPS) {
        int v = 0x1FF - (int)(keys[k] & 0xFFFFFFFFull);
        float t = tanhf(sc_s[v]);
        const float4* srcp = (const float4*)(x + ((size_t)(gbase + v)) * CC);
        float4* dstp = (float4*)(out + ((size_t)g * KK + k) * CC);
        #pragma unroll
        for (int j = 0; j < 2; j++) {
            float4 a = srcp[lane + 32 * j];
            a.x *= t; a.y *= t; a.z *= t; a.w *= t;
            dstp[lane + 32 * j] = a;
        }
        if (lane == 0) {
            out[off_perm  + (size_t)g * KK + k] = (float)(gbase + v);
            out[off_batch + (size_t)g * KK + k] = (float)g;
        }
    }

    // ---- edge remap + keep (edges from L2 scratch) ----
    {
        const size_t eb = (size_t)g * epg;
        const int gk = g * KK;
        for (int e = tid; e < epg; e += NTHREADS) {
            unsigned v = g_packed[eb + e];
            int ns = newid_s[v >> 16];
            int nd = newid_s[v & 0xFFFFu];
            size_t ge = eb + e;
            if (ns >= 0 && nd >= 0) {
                out[off_ei + ge]             = (float)(gk + ns);
                out[off_ei + (size_t)E + ge] = (float)(gk + nd);
                out[off_keep + ge]           = 1.0f;
            } else {
                out[off_ei + ge]             = -1.0f;
                out[off_ei + (size_t)E + ge] = -1.0f;
                out[off_keep + ge]           = 0.0f;
            }
        }
    }
}

extern "C" void kernel_launch(void* const* d_in, const int* in_sizes, int n_in,
                              void* d_out, int out_size)
{
    const float* x  = (const float*)d_in[0];
    const void*  ei = d_in[1];
    const float* W  = (const float*)d_in[3];
    const float* b  = (const float*)d_in[4];

    long long N = (long long)in_sizes[0] / CC;
    long long E = (long long)in_sizes[1] / 2;
    int G   = (int)(N / RR);
    int epg = (int)(E / G);

    float* out = (float*)d_out;
    size_t GK        = (size_t)G * KK;
    size_t off_ei    = GK * CC;
    size_t off_keep  = off_ei + 2 * (size_t)E;
    size_t off_batch = off_keep + (size_t)E;
    size_t off_perm  = off_batch + GK;
    size_t off_score = off_perm + GK;

    // dynamic smem size (must match kernel layout)
    size_t fixed = (size_t)CC * 4 + 6 * 288 * 4 + (size_t)NWARPS * HB * 2;
    size_t uB    = ((size_t)epg * 2 > (size_t)SORTN * 8) ? (size_t)epg * 2
                                                         : (size_t)SORTN * 8;
    size_t smemB = fixed + uB + 64;

    probe_dtype_kernel<<<1, 32>>>((const int*)ei);
    pack_edges_kernel<<<2048, 256>>>(ei, E);
    sagpool_kernel<<<G, NTHREADS, smemB>>>(x, W, b, out, E, epg,
                                           off_ei, off_keep, off_batch,
                                           off_perm, off_score);
}

// round 9
// speedup vs baseline: 1.1741x; 1.1741x over previous
#include <cuda_runtime.h>
#include <math.h>

#define RR 273
#define CC 256
#define KK 219
#define NTHREADS 384
#define SORTN 512
#define NWARPS 12
#define HB 280          // per-warp histogram stride (>= RR)
#define FULLM 0xFFFFFFFFu

__device__ int g_edge_is64;

__global__ void probe_dtype_kernel(const int* ei32) {
    if (threadIdx.x == 0) {
        int all_zero = 1;
        #pragma unroll
        for (int i = 1; i < 64; i += 2)
            if (ei32[i] != 0) { all_zero = 0; break; }
        g_edge_is64 = all_zero;
    }
}

__device__ __forceinline__ unsigned int ord_f32(float f) {
    unsigned int u = __float_as_uint(f);
    return (u & 0x80000000u) ? ~u : (u | 0x80000000u);
}

__global__ __launch_bounds__(NTHREADS, 3)
void sagpool_kernel(const float* __restrict__ x,
                    const void*  __restrict__ edge_index,
                    const float* __restrict__ Wp,
                    const float* __restrict__ bp,
                    float* __restrict__ out,
                    long long E, int epg,
                    size_t off_ei, size_t off_keep, size_t off_batch,
                    size_t off_perm, size_t off_score)
{
    extern __shared__ char smem[];
    // ---- layout (must match host sizing) ----
    float* wsh   = (float*)smem;                        // 256 floats
    float* h_s   = wsh + CC;                            // 288
    float* dis_s = h_s + 288;                           // 288
    float* sc_s  = dis_s + 288;                         // 288
    int* indeg_s = (int*)(sc_s + 288);                  // 288
    int* start_s = indeg_s + 288;                       // 288
    int* newid_s = start_s + 288;                       // 288
    unsigned short* hist = (unsigned short*)(newid_s + 288);  // NWARPS*HB u16
    unsigned int* ed = (unsigned int*)(((size_t)(hist + NWARPS * HB) + 7) & ~(size_t)7); // epg u32
    // union region: ssrc (epg u16) alive through score; keys (512 u64) after
    char* ub = (char*)(ed + epg);
    unsigned short* ssrc = (unsigned short*)ub;
    unsigned long long* keys = (unsigned long long*)ub;

    const int tid  = threadIdx.x;
    const int lane = tid & 31;
    const int warp = tid >> 5;
    const int g    = blockIdx.x;
    const long long gbase = (long long)g * RR;
    const int is64 = g_edge_is64;

    // ---- stage W, init small arrays ----
    if (tid < CC) wsh[tid] = Wp[tid];
    for (int v = tid; v < RR; v += NTHREADS) newid_s[v] = -1;
    for (int i = tid; i < NWARPS * HB; i += NTHREADS) hist[i] = 0;
    __syncthreads();

    // ---- phase A: h[v] as Eigen NEON row-major gemv (evalGemv path):
    //      4-lane packet accumulator, vfmaq (fused FMA),
    //      predux: (a0+a2)+(a1+a3).  Direct gmem row loads, one row/thread.
    if (tid < RR) {
        const float4* w4 = (const float4*)wsh;
        const float4* xr = (const float4*)(x + ((size_t)(gbase + tid)) * CC);
        float a0 = 0.f, a1 = 0.f, a2 = 0.f, a3 = 0.f;
        #pragma unroll 4
        for (int i = 0; i < 64; i++) {
            float4 v = xr[i];
            float4 w = w4[i];
            a0 = fmaf(v.x, w.x, a0);
            a1 = fmaf(v.y, w.y, a1);
            a2 = fmaf(v.z, w.z, a2);
            a3 = fmaf(v.w, w.w, a3);
        }
        h_s[tid] = __fadd_rn(__fadd_rn(a0, a2), __fadd_rn(a1, a3));
    }

    // ---- load edges -> packed local ids (src<<16 | dst) ----
    {
        const long long ebase = (long long)g * epg;
        if (is64) {
            const long long* p = (const long long*)edge_index;
            for (int e = tid; e < epg; e += NTHREADS) {
                int ls = (int)(p[ebase + e] - gbase);
                int ld = (int)(p[ebase + E + e] - gbase);
                ed[e] = ((unsigned)ls << 16) | (unsigned)ld;
            }
        } else {
            const int* p = (const int*)edge_index;
            for (int e = tid; e < epg; e += NTHREADS) {
                int ls = (int)(p[ebase + e] - gbase);
                int ld = (int)(p[ebase + E + e] - gbase);
                ed[e] = ((unsigned)ls << 16) | (unsigned)ld;
            }
        }
    }
    __syncthreads();   // h_s, ed, hist ready

    // ---- stable counting sort of edges by dst ----
    const int per = (((epg + NWARPS - 1) / NWARPS) + 31) & ~31;
    const int cbeg = warp * per;
    const int cend = min(epg, cbeg + per);

    // pass 1: per-warp-chunk histograms (deterministic)
    for (int base = cbeg; base < cend; base += 32) {
        int e = base + lane;
        bool act = e < cend;
        unsigned v = act ? ed[e] : 0u;
        int dst = act ? (int)(v & 0xFFFFu) : (512 + lane);
        unsigned m = __match_any_sync(FULLM, dst);
        int leader = __ffs(m) - 1;
        if (act && lane == leader)
            hist[warp * HB + dst] = (unsigned short)(hist[warp * HB + dst] + __popc(m));
        __syncwarp();
    }
    __syncthreads();

    // in-degree, dis = 1/sqrt(deg) (deg includes self-loop), both correctly rounded
    for (int v = tid; v < RR; v += NTHREADS) {
        int s = 0;
        #pragma unroll
        for (int w2 = 0; w2 < NWARPS; w2++) s += hist[w2 * HB + v];
        indeg_s[v] = s;
        dis_s[v] = __fdiv_rn(1.0f, __fsqrt_rn((float)(s + 1)));
    }
    __syncthreads();

    // exclusive scan of indeg -> start offsets (warp 0)
    if (warp == 0) {
        int lo = lane * 9;
        int acc = 0;
        #pragma unroll
        for (int i = 0; i < 9; i++) { int v = lo + i; if (v < RR) acc += indeg_s[v]; }
        int ex = acc;
        #pragma unroll
        for (int o = 1; o < 32; o <<= 1) {
            int t = __shfl_up_sync(FULLM, ex, o);
            if (lane >= o) ex += t;
        }
        ex -= acc;
        int run = ex;
        #pragma unroll
        for (int i = 0; i < 9; i++) {
            int v = lo + i;
            if (v < RR) { start_s[v] = run; run += indeg_s[v]; }
        }
    }
    __syncthreads();

    // per-(warp,dst) base pointers (in place, positions < 8736 fit u16)
    for (int v = tid; v < RR; v += NTHREADS) {
        int s = start_s[v];
        #pragma unroll
        for (int w2 = 0; w2 < NWARPS; w2++) {
            int t = hist[w2 * HB + v];
            hist[w2 * HB + v] = (unsigned short)s;
            s += t;
        }
    }
    __syncthreads();

    // pass 2: stable placement of src ids into per-dst lists
    for (int base = cbeg; base < cend; base += 32) {
        int e = base + lane;
        bool act = e < cend;
        unsigned v = act ? ed[e] : 0u;
        int dst = act ? (int)(v & 0xFFFFu) : (512 + lane);
        unsigned m = __match_any_sync(FULLM, dst);
        int rank = __popc(m & ((1u << lane) - 1u));
        int pos = 0;
        if (act) pos = (int)hist[warp * HB + dst] + rank;
        __syncwarp();
        if (act) ssrc[pos] = (unsigned short)(v >> 16);
        int leader = __ffs(m) - 1;
        if (act && lane == leader)
            hist[warp * HB + dst] = (unsigned short)(hist[warp * HB + dst] + __popc(m));
        __syncwarp();
    }
    __syncthreads();

    // ---- score: strictly sequential in reference scatter order ----
    const float bval = bp[0];
    if (tid < RR) {
        int v = tid;
        float dv = dis_s[v];
        float acc = 0.f;
        int st = start_s[v], n = indeg_s[v];
        for (int i = 0; i < n; i++) {
            int src = ssrc[st + i];
            float c = __fmul_rn(__fmul_rn(dis_s[src], dv), h_s[src]);
            acc = __fadd_rn(acc, c);
        }
        float selfc = __fmul_rn(__fmul_rn(dv, dv), h_s[v]);
        acc = __fadd_rn(acc, selfc);
        float sc = __fadd_rn(acc, bval);
        sc_s[v] = sc;
        out[off_score + (size_t)gbase + v] = sc;
    }
    __syncthreads();

    // ---- sort keys (overlay: ssrc dead now) ----
    for (int v = tid; v < SORTN; v += NTHREADS) {
        if (v < RR) {
            keys[v] = ((unsigned long long)ord_f32(sc_s[v]) << 32)
                      | (unsigned long long)(0x1FFu - (unsigned)v);
        } else keys[v] = 0ull;
    }

    // bitonic sort descending (ties -> lower index first)
    for (int kk = 2; kk <= SORTN; kk <<= 1) {
        for (int j = kk >> 1; j > 0; j >>= 1) {
            __syncthreads();
            for (int t = tid; t < SORTN; t += NTHREADS) {
                int ixj = t ^ j;
                if (ixj > t) {
                    bool desc = ((t & kk) == 0);
                    unsigned long long a = keys[t], b2 = keys[ixj];
                    if ((a < b2) == desc) { keys[t] = b2; keys[ixj] = a; }
                }
            }
        }
    }
    __syncthreads();

    // ---- new-id map ----
    if (tid < KK) {
        int v = 0x1FF - (int)(keys[tid] & 0xFFFFFFFFull);
        newid_s[v] = tid;
    }
    __syncthreads();

    // ---- x_new / perm / batch_new (warp per selected row) ----
    for (int k = warp; k < KK; k += NWARPS) {
        int v = 0x1FF - (int)(keys[k] & 0xFFFFFFFFull);
        float t = tanhf(sc_s[v]);
        const float4* srcp = (const float4*)(x + ((size_t)(gbase + v)) * CC);
        float4* dstp = (float4*)(out + ((size_t)g * KK + k) * CC);
        #pragma unroll
        for (int j = 0; j < 2; j++) {
            float4 a = srcp[lane + 32 * j];
            a.x *= t; a.y *= t; a.z *= t; a.w *= t;
            dstp[lane + 32 * j] = a;
        }
        if (lane == 0) {
            out[off_perm  + (size_t)g * KK + k] = (float)(gbase + v);
            out[off_batch + (size_t)g * KK + k] = (float)g;
        }
    }

    // ---- edge remap + keep ----
    {
        const size_t ebase = (size_t)g * epg;
        const int gk = g * KK;
        for (int e = tid; e < epg; e += NTHREADS) {
            unsigned v = ed[e];
            int ns = newid_s[v >> 16];
            int nd = newid_s[v & 0xFFFFu];
            size_t ge = ebase + e;
            if (ns >= 0 && nd >= 0) {
                out[off_ei + ge]             = (float)(gk + ns);
                out[off_ei + (size_t)E + ge] = (float)(gk + nd);
                out[off_keep + ge]           = 1.0f;
            } else {
                out[off_ei + ge]             = -1.0f;
                out[off_ei + (size_t)E + ge] = -1.0f;
                out[off_keep + ge]           = 0.0f;
            }
        }
    }
}

extern "C" void kernel_launch(void* const* d_in, const int* in_sizes, int n_in,
                              void* d_out, int out_size)
{
    const float* x  = (const float*)d_in[0];
    const void*  ei = d_in[1];
    const float* W  = (const float*)d_in[3];
    const float* b  = (const float*)d_in[4];

    long long N = (long long)in_sizes[0] / CC;
    long long E = (long long)in_sizes[1] / 2;
    int G   = (int)(N / RR);
    int epg = (int)(E / G);

    float* out = (float*)d_out;
    size_t GK        = (size_t)G * KK;
    size_t off_ei    = GK * CC;
    size_t off_keep  = off_ei + 2 * (size_t)E;
    size_t off_batch = off_keep + (size_t)E;
    size_t off_perm  = off_batch + GK;
    size_t off_score = off_perm + GK;

    // dynamic smem size (must match kernel layout)
    size_t fixed = (size_t)CC * 4 + 6 * 288 * 4 + (size_t)NWARPS * HB * 2 + 8;
    size_t edB   = (size_t)epg * 4;
    size_t uB    = ((size_t)epg * 2 > (size_t)SORTN * 8) ? (size_t)epg * 2
                                                         : (size_t)SORTN * 8;
    size_t smemB = fixed + edB + uB + 64;

    static int attr_set = 0;
    if (!attr_set) {
        cudaFuncSetAttribute(sagpool_kernel,
                             cudaFuncAttributeMaxDynamicSharedMemorySize,
                             (int)smemB);
        attr_set = 1;
    }

    probe_dtype_kernel<<<1, 32>>>((const int*)ei);
    sagpool_kernel<<<G, NTHREADS, smemB>>>(x, ei, W, b, out, E, epg,
                                           off_ei, off_keep, off_batch,
                                           off_perm, off_score);
}

// round 10
// speedup vs baseline: 1.2356x; 1.0523x over previous
#include <cuda_runtime.h>
#include <math.h>

#define RR 273
#define CC 256
#define KK 219
#define NTHREADS 384
#define NWARPS 12
#define HB 280          // per-warp histogram stride (>= RR)
#define FULLM 0xFFFFFFFFu

__device__ int g_edge_is64;

__global__ void probe_dtype_kernel(const int* ei32) {
    if (threadIdx.x == 0) {
        int all_zero = 1;
        #pragma unroll
        for (int i = 1; i < 64; i += 2)
            if (ei32[i] != 0) { all_zero = 0; break; }
        g_edge_is64 = all_zero;
    }
}

__device__ __forceinline__ unsigned int ord_f32(float f) {
    unsigned int u = __float_as_uint(f);
    return (u & 0x80000000u) ? ~u : (u | 0x80000000u);
}

__global__ __launch_bounds__(NTHREADS, 3)
void sagpool_kernel(const float* __restrict__ x,
                    const void*  __restrict__ edge_index,
                    const float* __restrict__ Wp,
                    const float* __restrict__ bp,
                    float* __restrict__ out,
                    long long E, int epg,
                    size_t off_ei, size_t off_keep, size_t off_batch,
                    size_t off_perm, size_t off_score)
{
    extern __shared__ char smem[];
    // ---- layout (must match host sizing) ----
    float* wsh   = (float*)smem;                        // 256 floats
    float* h_s   = wsh + CC;                            // 288
    float* dis_s = h_s + 288;                           // 288
    float* sc_s  = dis_s + 288;                         // 288
    int* indeg_s = (int*)(sc_s + 288);                  // 288
    int* start_s = indeg_s + 288;                       // 288
    int* newid_s = start_s + 288;                       // 288
    unsigned short* hist = (unsigned short*)(newid_s + 288);  // NWARPS*HB u16
    unsigned int* ed = (unsigned int*)(((size_t)(hist + NWARPS * HB) + 7) & ~(size_t)7); // epg u32
    // union region: ssrc (epg u16) alive through score; keys+sel after
    char* ub = (char*)(ed + epg);
    unsigned short* ssrc = (unsigned short*)ub;
    unsigned long long* keys = (unsigned long long*)ub;        // RR u64
    unsigned short* sel = (unsigned short*)(keys + 288);       // KK u16

    const int tid  = threadIdx.x;
    const int lane = tid & 31;
    const int warp = tid >> 5;
    const int g    = blockIdx.x;
    const long long gbase = (long long)g * RR;
    const int is64 = g_edge_is64;

    // ---- stage W, init small arrays ----
    if (tid < CC) wsh[tid] = Wp[tid];
    for (int i = tid; i < NWARPS * HB; i += NTHREADS) hist[i] = 0;
    __syncthreads();

    // ---- phase A: h[v] as Eigen NEON row-major gemv (evalGemv path):
    //      4-lane packet accumulator, vfmaq (fused FMA),
    //      predux: (a0+a2)+(a1+a3).  Direct gmem row loads, one row/thread.
    if (tid < RR) {
        const float4* w4 = (const float4*)wsh;
        const float4* xr = (const float4*)(x + ((size_t)(gbase + tid)) * CC);
        float a0 = 0.f, a1 = 0.f, a2 = 0.f, a3 = 0.f;
        #pragma unroll 4
        for (int i = 0; i < 64; i++) {
            float4 v = xr[i];
            float4 w = w4[i];
            a0 = fmaf(v.x, w.x, a0);
            a1 = fmaf(v.y, w.y, a1);
            a2 = fmaf(v.z, w.z, a2);
            a3 = fmaf(v.w, w.w, a3);
        }
        h_s[tid] = __fadd_rn(__fadd_rn(a0, a2), __fadd_rn(a1, a3));
    }

    // ---- load edges -> packed local ids (src<<16 | dst) ----
    {
        const long long ebase = (long long)g * epg;
        if (is64) {
            const long long* p = (const long long*)edge_index;
            for (int e = tid; e < epg; e += NTHREADS) {
                int ls = (int)(p[ebase + e] - gbase);
                int ld = (int)(p[ebase + E + e] - gbase);
                ed[e] = ((unsigned)ls << 16) | (unsigned)ld;
            }
        } else {
            const int* p = (const int*)edge_index;
            for (int e = tid; e < epg; e += NTHREADS) {
                int ls = (int)(p[ebase + e] - gbase);
                int ld = (int)(p[ebase + E + e] - gbase);
                ed[e] = ((unsigned)ls << 16) | (unsigned)ld;
            }
        }
    }
    __syncthreads();   // h_s, ed, hist ready

    // ---- stable counting sort of edges by dst ----
    const int per = (((epg + NWARPS - 1) / NWARPS) + 31) & ~31;
    const int cbeg = warp * per;
    const int cend = min(epg, cbeg + per);

    // pass 1: per-warp-chunk histograms (deterministic)
    for (int base = cbeg; base < cend; base += 32) {
        int e = base + lane;
        bool act = e < cend;
        unsigned v = act ? ed[e] : 0u;
        int dst = act ? (int)(v & 0xFFFFu) : (512 + lane);
        unsigned m = __match_any_sync(FULLM, dst);
        int leader = __ffs(m) - 1;
        if (act && lane == leader)
            hist[warp * HB + dst] = (unsigned short)(hist[warp * HB + dst] + __popc(m));
        __syncwarp();
    }
    __syncthreads();

    // in-degree, dis = 1/sqrt(deg) (deg includes self-loop), both correctly rounded
    for (int v = tid; v < RR; v += NTHREADS) {
        int s = 0;
        #pragma unroll
        for (int w2 = 0; w2 < NWARPS; w2++) s += hist[w2 * HB + v];
        indeg_s[v] = s;
        dis_s[v] = __fdiv_rn(1.0f, __fsqrt_rn((float)(s + 1)));
    }
    __syncthreads();

    // exclusive scan of indeg -> start offsets (warp 0)
    if (warp == 0) {
        int lo = lane * 9;
        int acc = 0;
        #pragma unroll
        for (int i = 0; i < 9; i++) { int v = lo + i; if (v < RR) acc += indeg_s[v]; }
        int ex = acc;
        #pragma unroll
        for (int o = 1; o < 32; o <<= 1) {
            int t = __shfl_up_sync(FULLM, ex, o);
            if (lane >= o) ex += t;
        }
        ex -= acc;
        int run = ex;
        #pragma unroll
        for (int i = 0; i < 9; i++) {
            int v = lo + i;
            if (v < RR) { start_s[v] = run; run += indeg_s[v]; }
        }
    }
    __syncthreads();

    // per-(warp,dst) base pointers (in place, positions < 8736 fit u16)
    for (int v = tid; v < RR; v += NTHREADS) {
        int s = start_s[v];
        #pragma unroll
        for (int w2 = 0; w2 < NWARPS; w2++) {
            int t = hist[w2 * HB + v];
            hist[w2 * HB + v] = (unsigned short)s;
            s += t;
        }
    }
    __syncthreads();

    // pass 2: stable placement of src ids into per-dst lists
    for (int base = cbeg; base < cend; base += 32) {
        int e = base + lane;
        bool act = e < cend;
        unsigned v = act ? ed[e] : 0u;
        int dst = act ? (int)(v & 0xFFFFu) : (512 + lane);
        unsigned m = __match_any_sync(FULLM, dst);
        int rank = __popc(m & ((1u << lane) - 1u));
        int pos = 0;
        if (act) pos = (int)hist[warp * HB + dst] + rank;
        __syncwarp();
        if (act) ssrc[pos] = (unsigned short)(v >> 16);
        int leader = __ffs(m) - 1;
        if (act && lane == leader)
            hist[warp * HB + dst] = (unsigned short)(hist[warp * HB + dst] + __popc(m));
        __syncwarp();
    }
    __syncthreads();

    // ---- score: strictly sequential in reference scatter order ----
    const float bval = bp[0];
    if (tid < RR) {
        int v = tid;
        float dv = dis_s[v];
        float acc = 0.f;
        int st = start_s[v], n = indeg_s[v];
        for (int i = 0; i < n; i++) {
            int src = ssrc[st + i];
            float c = __fmul_rn(__fmul_rn(dis_s[src], dv), h_s[src]);
            acc = __fadd_rn(acc, c);
        }
        float selfc = __fmul_rn(__fmul_rn(dv, dv), h_s[v]);
        acc = __fadd_rn(acc, selfc);
        float sc = __fadd_rn(acc, bval);
        sc_s[v] = sc;
        out[off_score + (size_t)gbase + v] = sc;
    }
    __syncthreads();   // score done; ssrc dead -> keys/sel may overwrite

    // ---- build rank keys (unique: index tie-break) ----
    if (tid < RR)
        keys[tid] = ((unsigned long long)ord_f32(sc_s[tid]) << 32)
                    | (unsigned long long)(0x1FFu - (unsigned)tid);
    __syncthreads();

    // ---- rank-based top-K selection (no sort, no barriers in loop):
    //      rank(v) = #{u : key_u > key_v}; ranks are a permutation of 0..RR-1.
    if (tid < RR) {
        unsigned long long mk = keys[tid];
        int rank = 0;
        #pragma unroll 3
        for (int u = 0; u < RR; u++)
            rank += (keys[u] > mk) ? 1 : 0;
        newid_s[tid] = (rank < KK) ? rank : -1;
        if (rank < KK) sel[rank] = (unsigned short)tid;
    } else if (tid < 2 * RR) {
        // nothing
    }
    __syncthreads();

    // ---- x_new / perm / batch_new (warp per selected row) ----
    for (int k = warp; k < KK; k += NWARPS) {
        int v = sel[k];
        float t = tanhf(sc_s[v]);
        const float4* srcp = (const float4*)(x + ((size_t)(gbase + v)) * CC);
        float4* dstp = (float4*)(out + ((size_t)g * KK + k) * CC);
        #pragma unroll
        for (int j = 0; j < 2; j++) {
            float4 a = srcp[lane + 32 * j];
            a.x *= t; a.y *= t; a.z *= t; a.w *= t;
            dstp[lane + 32 * j] = a;
        }
        if (lane == 0) {
            out[off_perm  + (size_t)g * KK + k] = (float)(gbase + v);
            out[off_batch + (size_t)g * KK + k] = (float)g;
        }
    }

    // ---- edge remap + keep ----
    {
        const size_t ebase = (size_t)g * epg;
        const int gk = g * KK;
        for (int e = tid; e < epg; e += NTHREADS) {
            unsigned v = ed[e];
            int ns = newid_s[v >> 16];
            int nd = newid_s[v & 0xFFFFu];
            size_t ge = ebase + e;
            if (ns >= 0 && nd >= 0) {
                out[off_ei + ge]             = (float)(gk + ns);
                out[off_ei + (size_t)E + ge] = (float)(gk + nd);
                out[off_keep + ge]           = 1.0f;
            } else {
                out[off_ei + ge]             = -1.0f;
                out[off_ei + (size_t)E + ge] = -1.0f;
                out[off_keep + ge]           = 0.0f;
            }
        }
    }
}

extern "C" void kernel_launch(void* const* d_in, const int* in_sizes, int n_in,
                              void* d_out, int out_size)
{
    const float* x  = (const float*)d_in[0];
    const void*  ei = d_in[1];
    const float* W  = (const float*)d_in[3];
    const float* b  = (const float*)d_in[4];

    long long N = (long long)in_sizes[0] / CC;
    long long E = (long long)in_sizes[1] / 2;
    int G   = (int)(N / RR);
    int epg = (int)(E / G);

    float* out = (float*)d_out;
    size_t GK        = (size_t)G * KK;
    size_t off_ei    = GK * CC;
    size_t off_keep  = off_ei + 2 * (size_t)E;
    size_t off_batch = off_keep + (size_t)E;
    size_t off_perm  = off_batch + GK;
    size_t off_score = off_perm + GK;

    // dynamic smem size (must match kernel layout)
    size_t fixed = (size_t)CC * 4 + 6 * 288 * 4 + (size_t)NWARPS * HB * 2 + 8;
    size_t edB   = (size_t)epg * 4;
    size_t keysB = 288 * 8 + 224 * 2;
    size_t uB    = ((size_t)epg * 2 > keysB) ? (size_t)epg * 2 : keysB;
    size_t smemB = fixed + edB + uB + 64;

    static int attr_set = 0;
    if (!attr_set) {
        cudaFuncSetAttribute(sagpool_kernel,
                             cudaFuncAttributeMaxDynamicSharedMemorySize,
                             (int)smemB);
        attr_set = 1;
    }

    probe_dtype_kernel<<<1, 32>>>((const int*)ei);
    sagpool_kernel<<<G, NTHREADS, smemB>>>(x, ei, W, b, out, E, epg,
                                           off_ei, off_keep, off_batch,
                                           off_perm, off_score);
}